// round 16
// baseline (speedup 1.0000x reference)
#include <cuda_runtime.h>
#include <cuda_bf16.h>
#include <cuda_fp16.h>
#include <math.h>
#include <stdint.h>

// Problem constants
#define BB   32
#define NN   1024
#define CIN  64
#define CO   128
#define KNN  16
#define BNROWS (BB*NN)          // 32768
#define ROWS   (BNROWS*KNN)     // 524288
#define GB     (ROWS/64)        // 8192 gemm blocks (64-row tiles)
#define EPSV 1e-5f

// ------------------------- device scratch (static, no allocs) ----------------
static __device__ int    g_idx[ROWS];                 // 2 MB
static __device__ float  g_center[BNROWS*CO];         // 16 MB
static __device__ __half g_h[BNROWS*CO];              // 8 MB (fp16 neighbor term)
static __device__ float  g_sc[BNROWS*CO];             // 16 MB
static __device__ __half g_x1[(size_t)ROWS*CO];       // 134 MB
static __device__ __half g_x2[(size_t)ROWS*CO];       // 134 MB
static __device__ float  g_part[GB*256];              // 8 MB
static __device__ float  g_partsc[256*256];           // 256 KB
static __device__ float  g_coef[4*256];               // (a[128],d[128]) x4
static __device__ __half g_w1h[CO*CO];
static __device__ __half g_w2h[CO*CO];

// ------------------------- PTX helpers ---------------------------------------
__device__ __forceinline__ uint32_t smem_u32(const void* p) {
    uint32_t a;
    asm("{ .reg .u64 t; cvta.to.shared.u64 t, %1; cvt.u32.u64 %0, t; }" : "=r"(a) : "l"(p));
    return a;
}
__device__ __forceinline__ void ldsm4(uint32_t* r, uint32_t addr) {
    asm volatile("ldmatrix.sync.aligned.m8n8.x4.shared.b16 {%0,%1,%2,%3}, [%4];"
        : "=r"(r[0]), "=r"(r[1]), "=r"(r[2]), "=r"(r[3]) : "r"(addr));
}
__device__ __forceinline__ void mma_f16(float* c, const uint32_t* a, uint32_t b0, uint32_t b1) {
    asm volatile("mma.sync.aligned.m16n8k16.row.col.f32.f16.f16.f32 "
        "{%0,%1,%2,%3}, {%4,%5,%6,%7}, {%8,%9}, {%0,%1,%2,%3};"
        : "+f"(c[0]), "+f"(c[1]), "+f"(c[2]), "+f"(c[3])
        : "r"(a[0]), "r"(a[1]), "r"(a[2]), "r"(a[3]), "r"(b0), "r"(b1));
}
__device__ __forceinline__ uint32_t packh2(__half a, __half b) {
    return (uint32_t)__half_as_ushort(a) | ((uint32_t)__half_as_ushort(b) << 16);
}
__device__ __forceinline__ void cp_async16(uint32_t s, const void* g) {
    asm volatile("cp.async.cg.shared.global [%0], [%1], 16;" :: "r"(s), "l"(g) : "memory");
}
__device__ __forceinline__ void cp_commit() {
    asm volatile("cp.async.commit_group;" ::: "memory");
}
template<int N> __device__ __forceinline__ void cp_wait() {
    asm volatile("cp.async.wait_group %0;" :: "n"(N) : "memory");
}

// ------------------------- dynamic smem layout (bytes) ------------------------
// 64-row tiles: 75264 B -> 3 CTAs/SM.
#define DB_BH    0          // 34816 (B fp16, row stride 272 B)
#define DB_A     34816      // 4 x 5120 (A fp16 64 rows, stride 80 B) -> 55296
#define DB_RAW   55296      // 4 x 4096 raw fp16 (64 rows x 64 B) -> 71680
#define DB_CTR   71680      // 2048 (center tile: 4 bn x 128 f32, gemm1 only)
#define DB_SA    73728      // 512
#define DB_SD    74240      // 512
#define DB_OFFH  74752      // 256
#define DB_TOTAL 75264

// ------------------------- 0) W fp16 precompute -------------------------------
__global__ void whalf_kernel(const float* __restrict__ W1, const float* __restrict__ W2,
                             __half* __restrict__ w1h, __half* __restrict__ w2h) {
    int i = blockIdx.x * 256 + threadIdx.x;
    w1h[i] = __float2half_rn(W1[i]);
    w2h[i] = __float2half_rn(W2[i]);
}

// ------------------------- 1) kNN: warp per query, register-resident ---------
__global__ __launch_bounds__(256)
void knn_kernel(const float* __restrict__ pts, int* __restrict__ idxout) {
    __shared__ float sx[NN], sy[NN], sz[NN], sxx[NN];
    int t = threadIdx.x;
    int wid = t >> 5, lane = t & 31;
    int blk = blockIdx.x;
    int b = blk >> 7;
    int n = ((blk & 127) << 3) + wid;
    const float* P = pts + (size_t)b * 3 * NN;
    for (int m = t; m < NN; m += 256) {
        float x = P[m], y = P[NN + m], z = P[2*NN + m];
        sx[m] = x; sy[m] = y; sz[m] = z;
        sxx[m] = x*x + y*y + z*z;
    }
    __syncthreads();
    float qx = sx[n], qy = sy[n], qz = sz[n], qxx = sxx[n];
    float d[32];
    #pragma unroll
    for (int j = 0; j < 32; j++) {
        int m = j*32 + lane;
        float dd = 2.f*(qx*sx[m] + qy*sy[m] + qz*sz[m]) - qxx - sxx[m];
        d[j] = (m == n) ? -INFINITY : dd;
    }
    int* op = idxout + ((size_t)b*NN + n) * KNN;
    unsigned alive = 0xffffffffu;
    for (int r = 0; r < KNN; r++) {
        float bv = -INFINITY; int bj = 0;
        #pragma unroll
        for (int j = 0; j < 32; j++) {
            float dj = (alive & (1u << j)) ? d[j] : -INFINITY;
            if (dj > bv) { bv = dj; bj = j; }
        }
        int bi = bj*32 + lane;
        #pragma unroll
        for (int s = 16; s > 0; s >>= 1) {
            float ov = __shfl_down_sync(0xffffffffu, bv, s);
            int   oi = __shfl_down_sync(0xffffffffu, bi, s);
            if (ov > bv || (ov == bv && oi < bi)) { bv = ov; bi = oi; }
        }
        bi = __shfl_sync(0xffffffffu, bi, 0);
        if (lane == 0) op[r] = bi;
        if ((bi & 31) == lane) alive &= ~(1u << (bi >> 5));
    }
}

// ------------------------- 2) per-point GEMVs --------------------------------
__global__ void feat_kernel(const float* __restrict__ f,
                            const float* __restrict__ W0,
                            const float* __restrict__ Wsc,
                            float* __restrict__ center,
                            __half* __restrict__ h,
                            float* __restrict__ sc) {
    __shared__ float fs[CIN][16];
    int base = blockIdx.x * 16;
    int b = base >> 10, n0 = base & 1023;
    int t = threadIdx.x;
    #pragma unroll
    for (int i = 0; i < 8; i++) {
        int idx = t + 128*i;
        int c = idx >> 4, j = idx & 15;
        fs[c][j] = f[(size_t)b*CIN*NN + c*NN + n0 + j];
    }
    __syncthreads();
    int o = t;
    float ctr[16], hh[16], ss[16];
    #pragma unroll
    for (int j = 0; j < 16; j++) { ctr[j]=0.f; hh[j]=0.f; ss[j]=0.f; }
    for (int c = 0; c < CIN; c++) {
        float w0a = W0[o*128 + c];
        float w0b = W0[o*128 + 64 + c];
        float ws  = Wsc[o*64 + c];
        float wc  = w0a - w0b;
        const float* fr = fs[c];
        #pragma unroll
        for (int j = 0; j < 16; j++) {
            float fv = fr[j];
            ctr[j] = fmaf(wc,  fv, ctr[j]);
            hh[j]  = fmaf(w0b, fv, hh[j]);
            ss[j]  = fmaf(ws,  fv, ss[j]);
        }
    }
    #pragma unroll
    for (int j = 0; j < 16; j++) {
        int row = base + j;
        center[row*CO + o] = ctr[j];
        h[row*CO + o]      = __float2half_rn(hh[j]);
        sc[row*CO + o]     = ss[j];
    }
}

// ------------------------- 3) layer-0 stats only (h fp16) --------------------
__global__ void buildstats_kernel(const float* __restrict__ center,
                                  const __half* __restrict__ h,
                                  const int* __restrict__ idx,
                                  float* __restrict__ part) {
    __shared__ float red[8][132];
    int t = threadIdx.x;
    int oq = (t & 31) << 2;
    int strip = t >> 5;
    int bn = blockIdx.x * 8 + strip;
    int b = bn >> 10;
    float4 c4 = *reinterpret_cast<const float4*>(&center[bn*CO + oq]);
    const int* ip = idx + bn*KNN;
    float s0=0,s1=0,s2=0,s3=0, q0=0,q1=0,q2=0,q3=0;
    #pragma unroll
    for (int k = 0; k < KNN; k++) {
        int gi = ip[k];
        uint2 hv = *reinterpret_cast<const uint2*>(&h[(b*NN + gi)*CO + oq]);
        float2 h01 = __half22float2(*reinterpret_cast<const __half2*>(&hv.x));
        float2 h23 = __half22float2(*reinterpret_cast<const __half2*>(&hv.y));
        float vx = c4.x + h01.x, vy = c4.y + h01.y, vz = c4.z + h23.x, vw = c4.w + h23.y;
        s0 += vx; s1 += vy; s2 += vz; s3 += vw;
        q0 = fmaf(vx,vx,q0); q1 = fmaf(vy,vy,q1); q2 = fmaf(vz,vz,q2); q3 = fmaf(vw,vw,q3);
    }
    red[strip][oq+0]=s0; red[strip][oq+1]=s1; red[strip][oq+2]=s2; red[strip][oq+3]=s3;
    __syncthreads();
    if (t < 128) {
        float s = 0;
        #pragma unroll
        for (int q = 0; q < 8; q++) s += red[q][t];
        part[blockIdx.x*256 + t] = s;
    }
    __syncthreads();
    red[strip][oq+0]=q0; red[strip][oq+1]=q1; red[strip][oq+2]=q2; red[strip][oq+3]=q3;
    __syncthreads();
    if (t < 128) {
        float s = 0;
        #pragma unroll
        for (int q = 0; q < 8; q++) s += red[q][t];
        part[blockIdx.x*256 + 128 + t] = s;
    }
}

// ------------------------- 4) stats: partials -> (a, d) ----------------------
__global__ void stats_kernel(const float* __restrict__ part, int nparts,
                             const float* __restrict__ g, const float* __restrict__ bt,
                             float* __restrict__ coef, float invM) {
    __shared__ float ss[256], qq[256];
    int o = blockIdx.x, t = threadIdx.x;
    float s = 0.f, q = 0.f;
    for (int p = t; p < nparts; p += 256) {
        s += part[p*256 + o];
        q += part[p*256 + 128 + o];
    }
    ss[t] = s; qq[t] = q;
    __syncthreads();
    for (int st = 128; st > 0; st >>= 1) {
        if (t < st) { ss[t] += ss[t+st]; qq[t] += qq[t+st]; }
        __syncthreads();
    }
    if (t == 0) {
        float mean = ss[0] * invM;
        float var  = qq[0] * invM - mean*mean;
        float a = g[o] / sqrtf(var + EPSV);
        coef[o] = a;
        coef[128 + o] = bt[o] - mean * a;
    }
}

// coalesced partial-sum over sc (rows x 128), 128 rows per block
__global__ void colpart_kernel(const float* __restrict__ X, float* __restrict__ part) {
    __shared__ float sm0[2][128], sm1[2][128];
    int t = threadIdx.x;
    int o = t & 127, hf = t >> 7;
    int r0 = blockIdx.x * 128 + hf * 64;
    float s = 0.f, q = 0.f;
    for (int i = 0; i < 64; i++) {
        float v = X[(size_t)(r0 + i)*CO + o];
        s += v; q = fmaf(v, v, q);
    }
    sm0[hf][o] = s; sm1[hf][o] = q;
    __syncthreads();
    if (t < 128) {
        part[blockIdx.x*256 + t]       = sm0[0][t] + sm0[1][t];
        part[blockIdx.x*256 + 128 + t] = sm1[0][t] + sm1[1][t];
    }
}

// ------------------------- 64-row full-K staged fp16 GEMM --------------------
// 256 threads, tile 64m x 128n, K=128. Warp grid 2m x 4n, warp tile 32x32.
// All raw A staged via cp.async up-front; barrier-free mma loop; 3 CTAs/SM.

__device__ __forceinline__ void issue_raw(bool fused, uint32_t sb,
                                          const __half* __restrict__ X16,
                                          const __half* __restrict__ h16,
                                          const int* offH, size_t mbase,
                                          int cq, int buf, int t) {
    uint32_t dst0 = sb + DB_RAW + (uint32_t)(buf * 4096);
    // 64 rows x 64 B, 16B chunks: 256 chunks / 256 thr = 1 each
    int row = t >> 2, c16 = t & 3;
    const __half* src = fused ? (h16 + offH[row] + cq + c16*8)
                              : (X16 + (mbase + row)*CO + cq + c16*8);
    cp_async16(dst0 + (uint32_t)(row*64 + c16*16), src);
}

__device__ __forceinline__ void convert_raw(bool fused, char* smem,
                                            const float* sa, const float* sd,
                                            int cq, int buf, char* abuf, int t) {
    const char* raw = smem + DB_RAW + buf * 4096;
    const float* ctr = (const float*)(smem + DB_CTR);
    #pragma unroll
    for (int i = 0; i < 2; i++) {
        int e = t + 256*i;           // 512 vec4 ops
        int c4 = e & 7, m = e >> 3;
        int c0 = c4*4;
        uint2 hv = *reinterpret_cast<const uint2*>(raw + m*64 + c0*2);
        float2 f01 = __half22float2(*reinterpret_cast<const __half2*>(&hv.x));
        float2 f23 = __half22float2(*reinterpret_cast<const __half2*>(&hv.y));
        float v0 = f01.x, v1 = f01.y, v2 = f23.x, v3 = f23.y;
        if (fused) {
            float4 cv = *reinterpret_cast<const float4*>(ctr + (m >> 4)*CO + cq + c0);
            v0 += cv.x; v1 += cv.y; v2 += cv.z; v3 += cv.w;
        }
        v0 = fmaxf(fmaf(sa[cq+c0+0], v0, sd[cq+c0+0]), 0.f);
        v1 = fmaxf(fmaf(sa[cq+c0+1], v1, sd[cq+c0+1]), 0.f);
        v2 = fmaxf(fmaf(sa[cq+c0+2], v2, sd[cq+c0+2]), 0.f);
        v3 = fmaxf(fmaf(sa[cq+c0+3], v3, sd[cq+c0+3]), 0.f);
        __half h0 = __float2half_rn(v0), h1 = __float2half_rn(v1);
        __half h2 = __float2half_rn(v2), h3 = __float2half_rn(v3);
        *reinterpret_cast<uint2*>(abuf + m*80 + c0*2) =
            make_uint2(packh2(h0, h1), packh2(h2, h3));
    }
}

__device__ __forceinline__ void gemm_mma_core(
    bool fused, const __half* __restrict__ X16,
    const float* __restrict__ center, const __half* __restrict__ h16,
    const int* __restrict__ idx,
    const __half* __restrict__ Wh,
    const float* __restrict__ coef,
    __half* __restrict__ Y, float* __restrict__ part)
{
    extern __shared__ char smem[];
    int t = threadIdx.x;
    int wid = t >> 5, lane = t & 31;
    int wm = wid >> 2, wn = wid & 3;       // warp grid 2m x 4n
    int m0w = wm * 32, n0w = wn * 32;
    int g = lane >> 2, q = lane & 3;
    size_t mbase = (size_t)blockIdx.x * 64;

    float* sa = (float*)(smem + DB_SA);
    float* sd = (float*)(smem + DB_SD);
    int* offH = (int*)(smem + DB_OFFH);
    uint32_t sb = smem_u32(smem);

    if (t < 128) {
        sa[t] = coef[t];
        sd[t] = coef[128 + t];
    }
    if (fused && t < 64) {
        int G = (int)mbase + t;
        int bn = G >> 4;
        int gi = idx[G];
        offH[t] = ((bn >> 10) * NN + gi) * CO;
    }
    if (!fused) {
        #pragma unroll
        for (int kq = 0; kq < 4; kq++) {
            issue_raw(false, sb, X16, h16, nullptr, mbase, kq*32, kq, t);
            cp_commit();
        }
    }
    // load W into smem, rows stride 136 halves (68 u32)
    {
        const uint32_t* wh = reinterpret_cast<const uint32_t*>(Wh);
        uint32_t* bh = reinterpret_cast<uint32_t*>(smem + DB_BH);
        #pragma unroll
        for (int i = 0; i < 32; i++) {
            int e = t + 256*i;
            int c2 = e & 63, o = e >> 6;
            bh[o*68 + c2] = wh[e];
        }
    }
    if (fused) {
        __syncthreads();               // offH visible
        #pragma unroll
        for (int kq = 0; kq < 4; kq++) {
            issue_raw(true, sb, X16, h16, offH, mbase, kq*32, kq, t);
            cp_commit();
        }
        float* ctr = (float*)(smem + DB_CTR);
        int bn0 = blockIdx.x * 4;
        #pragma unroll
        for (int i = 0; i < 2; i++) {
            int e = t + 256*i;          // 512 floats
            ctr[e] = center[bn0*CO + e];
        }
    }
    cp_wait<0>();
    __syncthreads();

    #pragma unroll
    for (int kq = 0; kq < 4; kq++)
        convert_raw(fused, smem, sa, sd, kq*32, kq, smem + DB_A + kq*5120, t);
    __syncthreads();

    uint32_t aOffLane = (uint32_t)((m0w + (lane & 15)) * 80 + ((lane >> 4) << 4));
    uint32_t bRow = (uint32_t)(n0w + (lane & 7) + ((lane >> 4) << 3));
    uint32_t bHiBase = sb + DB_BH + bRow * 272 + (((lane >> 3) & 1) << 4);

    float acc[2][4][4];
    #pragma unroll
    for (int a = 0; a < 2; a++)
        #pragma unroll
        for (int b = 0; b < 4; b++)
            #pragma unroll
            for (int r = 0; r < 4; r++) acc[a][b][r] = 0.f;

    // barrier-free mainloop: 8 k16 steps
    #pragma unroll
    for (int kq = 0; kq < 4; kq++) {
        uint32_t aHi = sb + DB_A + (uint32_t)(kq*5120) + aOffLane;
        #pragma unroll
        for (int ks = 0; ks < 2; ks++) {
            uint32_t koffA = (uint32_t)(ks * 32);
            uint32_t koffB = (uint32_t)(kq * 64 + ks * 32);
            uint32_t bh0[4], bh1[4];
            ldsm4(bh0, bHiBase + koffB);
            ldsm4(bh1, bHiBase + 16*272 + koffB);
            #pragma unroll
            for (int a = 0; a < 2; a++) {
                uint32_t ahi[4];
                ldsm4(ahi, aHi + (uint32_t)(a*16*80) + koffA);
                mma_f16(acc[a][0], ahi, bh0[0], bh0[1]);
                mma_f16(acc[a][1], ahi, bh0[2], bh0[3]);
                mma_f16(acc[a][2], ahi, bh1[0], bh1[1]);
                mma_f16(acc[a][3], ahi, bh1[2], bh1[3]);
            }
        }
    }

    // epilogue: store Y (fp16) + BN partials (fp32)
    float ls[4][2], lq[4][2];
    #pragma unroll
    for (int b = 0; b < 4; b++) { ls[b][0]=0.f; ls[b][1]=0.f; lq[b][0]=0.f; lq[b][1]=0.f; }
    #pragma unroll
    for (int a = 0; a < 2; a++) {
        #pragma unroll
        for (int hf = 0; hf < 2; hf++) {
            int row = m0w + 16*a + g + 8*hf;
            __half* yr = Y + (mbase + row)*CO + n0w + 2*q;
            #pragma unroll
            for (int b = 0; b < 4; b++) {
                float c0 = acc[a][b][2*hf], c1 = acc[a][b][2*hf + 1];
                *reinterpret_cast<uint32_t*>(yr + 8*b) =
                    packh2(__float2half_rn(c0), __float2half_rn(c1));
                ls[b][0] += c0; ls[b][1] += c1;
                lq[b][0] = fmaf(c0, c0, lq[b][0]);
                lq[b][1] = fmaf(c1, c1, lq[b][1]);
            }
        }
    }
    #pragma unroll
    for (int b = 0; b < 4; b++) {
        #pragma unroll
        for (int p2 = 0; p2 < 2; p2++) {
            #pragma unroll
            for (int off = 4; off < 32; off <<= 1) {
                ls[b][p2] += __shfl_xor_sync(0xffffffffu, ls[b][p2], off);
                lq[b][p2] += __shfl_xor_sync(0xffffffffu, lq[b][p2], off);
            }
        }
    }
    __syncthreads();   // all warps past mma before overlaying A
    float* redS = (float*)(smem + DB_A);
    float* redQ = (float*)(smem + DB_A + 4096);
    if (lane < 4) {
        #pragma unroll
        for (int b = 0; b < 4; b++) {
            #pragma unroll
            for (int p2 = 0; p2 < 2; p2++) {
                int cs = 8*b + 2*lane + p2;
                redS[wid*32 + cs] = ls[b][p2];
                redQ[wid*32 + cs] = lq[b][p2];
            }
        }
    }
    __syncthreads();
    if (t < 128) {
        int wnc = t >> 5, cw = t & 31;
        float Sv = redS[wnc*32 + cw] + redS[(wnc+4)*32 + cw];
        float Qv = redQ[wnc*32 + cw] + redQ[(wnc+4)*32 + cw];
        part[blockIdx.x*256 + t]       = Sv;
        part[blockIdx.x*256 + 128 + t] = Qv;
    }
}

__global__ __launch_bounds__(256, 3)
void gemm1_mma(const float* __restrict__ center, const __half* __restrict__ h16,
               const int* __restrict__ idx,
               const __half* __restrict__ Wh,
               const float* __restrict__ coef, __half* __restrict__ Y,
               float* __restrict__ part) {
    gemm_mma_core(true, nullptr, center, h16, idx, Wh, coef, Y, part);
}

__global__ __launch_bounds__(256, 3)
void gemm2_mma(const __half* __restrict__ X16,
               const __half* __restrict__ Wh,
               const float* __restrict__ coef, __half* __restrict__ Y,
               float* __restrict__ part) {
    gemm_mma_core(false, X16, nullptr, nullptr, nullptr, Wh, coef, Y, part);
}

// ------------------------- final: mean_k relu(bn2) + bn_sc + relu, transpose -
__global__ void final_kernel(const __half* __restrict__ x2, const float* __restrict__ sc,
                             const float* __restrict__ coef2, const float* __restrict__ coefsc,
                             float* __restrict__ out) {
    __shared__ float tile[8*129];
    int t = threadIdx.x;
    int blk = blockIdx.x;
    int b = blk >> 7;
    int n0 = (blk & 127) << 3;
    #pragma unroll
    for (int i = 0; i < 4; i++) {
        int idx = t + 256*i;
        int o = idx & 127, nn = idx >> 7;
        int bn = b*NN + n0 + nn;
        float a2 = coef2[o], d2 = coef2[128 + o];
        const __half* xr = x2 + (size_t)bn * KNN * CO + o;
        float s = 0.f;
        #pragma unroll
        for (int k = 0; k < KNN; k++)
            s += fmaxf(fmaf(a2, __half2float(xr[k*CO]), d2), 0.f);
        float scv = sc[bn*CO + o];
        float as = coefsc[o], ds = coefsc[128 + o];
        tile[nn*129 + o] = fmaxf(fmaf(as, scv, ds) + s * (1.f/16.f), 0.f);
    }
    __syncthreads();
    #pragma unroll
    for (int i = 0; i < 4; i++) {
        int idx = t + 256*i;
        int nn = idx & 7, o = idx >> 3;
        out[(size_t)b*CO*NN + o*NN + n0 + nn] = tile[nn*129 + o];
    }
}

// ------------------------- host launcher -------------------------------------
extern "C" void kernel_launch(void* const* d_in, const int* in_sizes, int n_in,
                              void* d_out, int out_size) {
    const float* points   = (const float*)d_in[0];
    const float* features = (const float*)d_in[1];
    const float* W0  = (const float*)d_in[2];
    const float* g0  = (const float*)d_in[3];
    const float* b0  = (const float*)d_in[4];
    const float* W1  = (const float*)d_in[5];
    const float* g1  = (const float*)d_in[6];
    const float* b1  = (const float*)d_in[7];
    const float* W2  = (const float*)d_in[8];
    const float* g2  = (const float*)d_in[9];
    const float* b2  = (const float*)d_in[10];
    const float* Wsc = (const float*)d_in[11];
    const float* gsc = (const float*)d_in[12];
    const float* bsc = (const float*)d_in[13];
    float* out = (float*)d_out;

    void *p_idx, *p_center, *p_h, *p_sc, *p_x1, *p_x2, *p_part, *p_partsc, *p_coef;
    void *p_w1h, *p_w2h;
    cudaGetSymbolAddress(&p_idx,    g_idx);
    cudaGetSymbolAddress(&p_center, g_center);
    cudaGetSymbolAddress(&p_h,      g_h);
    cudaGetSymbolAddress(&p_sc,     g_sc);
    cudaGetSymbolAddress(&p_x1,     g_x1);
    cudaGetSymbolAddress(&p_x2,     g_x2);
    cudaGetSymbolAddress(&p_part,   g_part);
    cudaGetSymbolAddress(&p_partsc, g_partsc);
    cudaGetSymbolAddress(&p_coef,   g_coef);
    cudaGetSymbolAddress(&p_w1h,    g_w1h);
    cudaGetSymbolAddress(&p_w2h,    g_w2h);

    int*    idx    = (int*)p_idx;
    float*  center = (float*)p_center;
    __half* h      = (__half*)p_h;
    float*  sc     = (float*)p_sc;
    __half* x1     = (__half*)p_x1;
    __half* x2     = (__half*)p_x2;
    float*  part   = (float*)p_part;
    float*  partsc = (float*)p_partsc;
    float*  coef0  = (float*)p_coef;
    float*  coef1  = coef0 + 256;
    float*  coef2  = coef0 + 512;
    float*  coef3  = coef0 + 768;
    __half* w1h = (__half*)p_w1h;
    __half* w2h = (__half*)p_w2h;

    const float invM  = 1.f / (float)ROWS;
    const float invMs = 1.f / (float)BNROWS;

    cudaFuncSetAttribute(gemm1_mma, cudaFuncAttributeMaxDynamicSharedMemorySize, DB_TOTAL);
    cudaFuncSetAttribute(gemm2_mma, cudaFuncAttributeMaxDynamicSharedMemorySize, DB_TOTAL);

    whalf_kernel<<<64, 256>>>(W1, W2, w1h, w2h);
    knn_kernel<<<BNROWS/8, 256>>>(points, idx);
    feat_kernel<<<BNROWS/16, 128>>>(features, W0, Wsc, center, h, sc);
    buildstats_kernel<<<BNROWS/8, 256>>>(center, h, idx, part);
    colpart_kernel<<<256, 256>>>(sc, partsc);
    stats_kernel<<<128, 256>>>(part, BNROWS/8, g0, b0, coef0, invM);
    stats_kernel<<<128, 256>>>(partsc, 256, gsc, bsc, coef3, invMs);
    gemm1_mma<<<GB, 256, DB_TOTAL>>>(center, h, idx, w1h, coef0, x1, part);
    stats_kernel<<<128, 256>>>(part, GB, g1, b1, coef1, invM);
    gemm2_mma<<<GB, 256, DB_TOTAL>>>(x1, w2h, coef1, x2, part);
    stats_kernel<<<128, 256>>>(part, GB, g2, b2, coef2, invM);
    final_kernel<<<4096, 256>>>(x2, sc, coef2, coef3, out);
}

// round 17
// speedup vs baseline: 1.1005x; 1.1005x over previous
#include <cuda_runtime.h>
#include <cuda_bf16.h>
#include <cuda_fp16.h>
#include <math.h>
#include <stdint.h>

// Problem constants
#define BB   32
#define NN   1024
#define CIN  64
#define CO   128
#define KNN  16
#define BNROWS (BB*NN)          // 32768
#define ROWS   (BNROWS*KNN)     // 524288
#define GEMM_BLOCKS (ROWS/128)  // 4096
#define EPSV 1e-5f

// ------------------------- device scratch (static, no allocs) ----------------
static __device__ int    g_idx[ROWS];                 // 2 MB
static __device__ float  g_center[BNROWS*CO];         // 16 MB
static __device__ __half g_h[BNROWS*CO];              // 8 MB (fp16 neighbor term)
static __device__ float  g_sc[BNROWS*CO];             // 16 MB
static __device__ __half g_x1[(size_t)ROWS*CO];       // 134 MB (layer-1 out, fp16)
static __device__ __half g_x2[(size_t)ROWS*CO];       // 134 MB (layer-2 out, fp16)
static __device__ float  g_part[GEMM_BLOCKS*256];     // 4 MB
static __device__ float  g_partsc[256*256];           // 256 KB
static __device__ float  g_coef[4*256];               // (a[128],d[128]) x4
static __device__ __half g_w1h[CO*CO];                // fp16-rounded weights
static __device__ __half g_w2h[CO*CO];

// ------------------------- PTX helpers ---------------------------------------
__device__ __forceinline__ uint32_t smem_u32(const void* p) {
    uint32_t a;
    asm("{ .reg .u64 t; cvta.to.shared.u64 t, %1; cvt.u32.u64 %0, t; }" : "=r"(a) : "l"(p));
    return a;
}
__device__ __forceinline__ void ldsm4(uint32_t* r, uint32_t addr) {
    asm volatile("ldmatrix.sync.aligned.m8n8.x4.shared.b16 {%0,%1,%2,%3}, [%4];"
        : "=r"(r[0]), "=r"(r[1]), "=r"(r[2]), "=r"(r[3]) : "r"(addr));
}
__device__ __forceinline__ void mma_f16(float* c, const uint32_t* a, uint32_t b0, uint32_t b1) {
    asm volatile("mma.sync.aligned.m16n8k16.row.col.f32.f16.f16.f32 "
        "{%0,%1,%2,%3}, {%4,%5,%6,%7}, {%8,%9}, {%0,%1,%2,%3};"
        : "+f"(c[0]), "+f"(c[1]), "+f"(c[2]), "+f"(c[3])
        : "r"(a[0]), "r"(a[1]), "r"(a[2]), "r"(a[3]), "r"(b0), "r"(b1));
}
__device__ __forceinline__ uint32_t packh2(__half a, __half b) {
    return (uint32_t)__half_as_ushort(a) | ((uint32_t)__half_as_ushort(b) << 16);
}
__device__ __forceinline__ void cp_async16(uint32_t s, const void* g) {
    asm volatile("cp.async.cg.shared.global [%0], [%1], 16;" :: "r"(s), "l"(g) : "memory");
}
__device__ __forceinline__ void cp_commit() {
    asm volatile("cp.async.commit_group;" ::: "memory");
}
template<int N> __device__ __forceinline__ void cp_wait() {
    asm volatile("cp.async.wait_group %0;" :: "n"(N) : "memory");
}

// ------------------------- dynamic smem layout (bytes) ------------------------
// Full-K staging: barrier-free mma mainloop. 114176 B -> 2 CTAs/SM.
#define DB_BH    0          // 34816 (B fp16, row stride 272 B)
#define DB_A     34816      // 4 x 10240 (A fp16, row stride 80 B) -> 75776
#define DB_RAW   75776      // 4 x 8192 raw fp16 staging (row 64 B) -> 108544
#define DB_CTR   108544     // 4096 (center tile: 8 bn x 128 f32, gemm1 only)
#define DB_SA    112640     // 512
#define DB_SD    113152     // 512
#define DB_OFFH  113664     // 512
#define DB_TOTAL 114176

// ------------------------- 0) W fp16 precompute -------------------------------
__global__ void whalf_kernel(const float* __restrict__ W1, const float* __restrict__ W2,
                             __half* __restrict__ w1h, __half* __restrict__ w2h) {
    int i = blockIdx.x * 256 + threadIdx.x;   // 16384
    w1h[i] = __float2half_rn(W1[i]);
    w2h[i] = __float2half_rn(W2[i]);
}

// ------------------------- 1) kNN: warp per query, register-resident ---------
__global__ __launch_bounds__(256)
void knn_kernel(const float* __restrict__ pts, int* __restrict__ idxout) {
    __shared__ float sx[NN], sy[NN], sz[NN], sxx[NN];
    int t = threadIdx.x;
    int wid = t >> 5, lane = t & 31;
    int blk = blockIdx.x;
    int b = blk >> 7;
    int n = ((blk & 127) << 3) + wid;
    const float* P = pts + (size_t)b * 3 * NN;
    for (int m = t; m < NN; m += 256) {
        float x = P[m], y = P[NN + m], z = P[2*NN + m];
        sx[m] = x; sy[m] = y; sz[m] = z;
        sxx[m] = x*x + y*y + z*z;
    }
    __syncthreads();
    float qx = sx[n], qy = sy[n], qz = sz[n], qxx = sxx[n];
    float d[32];
    #pragma unroll
    for (int j = 0; j < 32; j++) {
        int m = j*32 + lane;
        float dd = 2.f*(qx*sx[m] + qy*sy[m] + qz*sz[m]) - qxx - sxx[m];
        d[j] = (m == n) ? -INFINITY : dd;
    }
    int* op = idxout + ((size_t)b*NN + n) * KNN;
    unsigned alive = 0xffffffffu;
    for (int r = 0; r < KNN; r++) {
        float bv = -INFINITY; int bj = 0;
        #pragma unroll
        for (int j = 0; j < 32; j++) {
            float dj = (alive & (1u << j)) ? d[j] : -INFINITY;
            if (dj > bv) { bv = dj; bj = j; }
        }
        int bi = bj*32 + lane;
        #pragma unroll
        for (int s = 16; s > 0; s >>= 1) {
            float ov = __shfl_down_sync(0xffffffffu, bv, s);
            int   oi = __shfl_down_sync(0xffffffffu, bi, s);
            if (ov > bv || (ov == bv && oi < bi)) { bv = ov; bi = oi; }
        }
        bi = __shfl_sync(0xffffffffu, bi, 0);
        if (lane == 0) op[r] = bi;
        if ((bi & 31) == lane) alive &= ~(1u << (bi >> 5));
    }
}

// ------------------------- 2) per-point GEMVs --------------------------------
__global__ void feat_kernel(const float* __restrict__ f,
                            const float* __restrict__ W0,
                            const float* __restrict__ Wsc,
                            float* __restrict__ center,
                            __half* __restrict__ h,
                            float* __restrict__ sc) {
    __shared__ float fs[CIN][16];
    int base = blockIdx.x * 16;
    int b = base >> 10, n0 = base & 1023;
    int t = threadIdx.x;
    #pragma unroll
    for (int i = 0; i < 8; i++) {
        int idx = t + 128*i;
        int c = idx >> 4, j = idx & 15;
        fs[c][j] = f[(size_t)b*CIN*NN + c*NN + n0 + j];
    }
    __syncthreads();
    int o = t;
    float ctr[16], hh[16], ss[16];
    #pragma unroll
    for (int j = 0; j < 16; j++) { ctr[j]=0.f; hh[j]=0.f; ss[j]=0.f; }
    for (int c = 0; c < CIN; c++) {
        float w0a = W0[o*128 + c];
        float w0b = W0[o*128 + 64 + c];
        float ws  = Wsc[o*64 + c];
        float wc  = w0a - w0b;
        const float* fr = fs[c];
        #pragma unroll
        for (int j = 0; j < 16; j++) {
            float fv = fr[j];
            ctr[j] = fmaf(wc,  fv, ctr[j]);
            hh[j]  = fmaf(w0b, fv, hh[j]);
            ss[j]  = fmaf(ws,  fv, ss[j]);
        }
    }
    #pragma unroll
    for (int j = 0; j < 16; j++) {
        int row = base + j;
        center[row*CO + o] = ctr[j];
        h[row*CO + o]      = __float2half_rn(hh[j]);
        sc[row*CO + o]     = ss[j];
    }
}

// ------------------------- 3) layer-0 stats only (h fp16) --------------------
__global__ void buildstats_kernel(const float* __restrict__ center,
                                  const __half* __restrict__ h,
                                  const int* __restrict__ idx,
                                  float* __restrict__ part) {
    __shared__ float red[8][132];
    int t = threadIdx.x;
    int oq = (t & 31) << 2;
    int strip = t >> 5;
    int bn = blockIdx.x * 8 + strip;
    int b = bn >> 10;
    float4 c4 = *reinterpret_cast<const float4*>(&center[bn*CO + oq]);
    const int* ip = idx + bn*KNN;
    float s0=0,s1=0,s2=0,s3=0, q0=0,q1=0,q2=0,q3=0;
    #pragma unroll
    for (int k = 0; k < KNN; k++) {
        int gi = ip[k];
        uint2 hv = *reinterpret_cast<const uint2*>(&h[(b*NN + gi)*CO + oq]);
        float2 h01 = __half22float2(*reinterpret_cast<const __half2*>(&hv.x));
        float2 h23 = __half22float2(*reinterpret_cast<const __half2*>(&hv.y));
        float vx = c4.x + h01.x, vy = c4.y + h01.y, vz = c4.z + h23.x, vw = c4.w + h23.y;
        s0 += vx; s1 += vy; s2 += vz; s3 += vw;
        q0 = fmaf(vx,vx,q0); q1 = fmaf(vy,vy,q1); q2 = fmaf(vz,vz,q2); q3 = fmaf(vw,vw,q3);
    }
    red[strip][oq+0]=s0; red[strip][oq+1]=s1; red[strip][oq+2]=s2; red[strip][oq+3]=s3;
    __syncthreads();
    if (t < 128) {
        float s = 0;
        #pragma unroll
        for (int q = 0; q < 8; q++) s += red[q][t];
        part[blockIdx.x*256 + t] = s;
    }
    __syncthreads();
    red[strip][oq+0]=q0; red[strip][oq+1]=q1; red[strip][oq+2]=q2; red[strip][oq+3]=q3;
    __syncthreads();
    if (t < 128) {
        float s = 0;
        #pragma unroll
        for (int q = 0; q < 8; q++) s += red[q][t];
        part[blockIdx.x*256 + 128 + t] = s;
    }
}

// ------------------------- 4) stats: partials -> (a, d) ----------------------
__global__ void stats_kernel(const float* __restrict__ part, int nparts,
                             const float* __restrict__ g, const float* __restrict__ bt,
                             float* __restrict__ coef, float invM) {
    __shared__ float ss[256], qq[256];
    int o = blockIdx.x, t = threadIdx.x;
    float s = 0.f, q = 0.f;
    for (int p = t; p < nparts; p += 256) {
        s += part[p*256 + o];
        q += part[p*256 + 128 + o];
    }
    ss[t] = s; qq[t] = q;
    __syncthreads();
    for (int st = 128; st > 0; st >>= 1) {
        if (t < st) { ss[t] += ss[t+st]; qq[t] += qq[t+st]; }
        __syncthreads();
    }
    if (t == 0) {
        float mean = ss[0] * invM;
        float var  = qq[0] * invM - mean*mean;
        float a = g[o] / sqrtf(var + EPSV);
        coef[o] = a;
        coef[128 + o] = bt[o] - mean * a;
    }
}

// coalesced partial-sum over sc (rows x 128), 128 rows per block
__global__ void colpart_kernel(const float* __restrict__ X, float* __restrict__ part) {
    __shared__ float sm0[2][128], sm1[2][128];
    int t = threadIdx.x;
    int o = t & 127, hf = t >> 7;
    int r0 = blockIdx.x * 128 + hf * 64;
    float s = 0.f, q = 0.f;
    for (int i = 0; i < 64; i++) {
        float v = X[(size_t)(r0 + i)*CO + o];
        s += v; q = fmaf(v, v, q);
    }
    sm0[hf][o] = s; sm1[hf][o] = q;
    __syncthreads();
    if (t < 128) {
        part[blockIdx.x*256 + t]       = sm0[0][t] + sm0[1][t];
        part[blockIdx.x*256 + 128 + t] = sm1[0][t] + sm1[1][t];
    }
}

// ------------------------- full-K staged fp16 GEMM ---------------------------
// 256 threads, tile 128m x 128n, K=128. All raw A staged up-front via cp.async;
// convert once; mma mainloop is barrier-free. (R15 best configuration.)

__device__ __forceinline__ void issue_raw(bool fused, uint32_t sb,
                                          const __half* __restrict__ X16,
                                          const __half* __restrict__ h16,
                                          const int* offH, size_t mbase,
                                          int cq, int buf, int t) {
    uint32_t dst0 = sb + DB_RAW + (uint32_t)(buf * 8192);
    #pragma unroll
    for (int i = 0; i < 2; i++) {
        int chunk = t + 256*i;
        int row = chunk >> 2, c16 = chunk & 3;
        const __half* src = fused ? (h16 + offH[row] + cq + c16*8)
                                  : (X16 + (mbase + row)*CO + cq + c16*8);
        cp_async16(dst0 + (uint32_t)(row*64 + c16*16), src);
    }
}

__device__ __forceinline__ void convert_raw(bool fused, char* smem,
                                            const float* sa, const float* sd,
                                            int cq, int buf, char* abuf, int t) {
    const char* raw = smem + DB_RAW + buf * 8192;
    const float* ctr = (const float*)(smem + DB_CTR);
    #pragma unroll
    for (int i = 0; i < 4; i++) {
        int e = t + 256*i;
        int c4 = e & 7, m = e >> 3;
        int c0 = c4*4;
        uint2 hv = *reinterpret_cast<const uint2*>(raw + m*64 + c0*2);
        float2 f01 = __half22float2(*reinterpret_cast<const __half2*>(&hv.x));
        float2 f23 = __half22float2(*reinterpret_cast<const __half2*>(&hv.y));
        float v0 = f01.x, v1 = f01.y, v2 = f23.x, v3 = f23.y;
        if (fused) {
            float4 cv = *reinterpret_cast<const float4*>(ctr + (m >> 4)*CO + cq + c0);
            v0 += cv.x; v1 += cv.y; v2 += cv.z; v3 += cv.w;
        }
        v0 = fmaxf(fmaf(sa[cq+c0+0], v0, sd[cq+c0+0]), 0.f);
        v1 = fmaxf(fmaf(sa[cq+c0+1], v1, sd[cq+c0+1]), 0.f);
        v2 = fmaxf(fmaf(sa[cq+c0+2], v2, sd[cq+c0+2]), 0.f);
        v3 = fmaxf(fmaf(sa[cq+c0+3], v3, sd[cq+c0+3]), 0.f);
        __half h0 = __float2half_rn(v0), h1 = __float2half_rn(v1);
        __half h2 = __float2half_rn(v2), h3 = __float2half_rn(v3);
        *reinterpret_cast<uint2*>(abuf + m*80 + c0*2) =
            make_uint2(packh2(h0, h1), packh2(h2, h3));
    }
}

__device__ __forceinline__ void gemm_mma_core(
    bool fused, const __half* __restrict__ X16,
    const float* __restrict__ center, const __half* __restrict__ h16,
    const int* __restrict__ idx,
    const __half* __restrict__ Wh,
    const float* __restrict__ coef,
    __half* __restrict__ Y, float* __restrict__ part)
{
    extern __shared__ char smem[];
    int t = threadIdx.x;
    int wid = t >> 5, lane = t & 31;
    int wm = wid >> 2, wn = wid & 3;       // warp grid 2m x 4n
    int m0w = wm * 64, n0w = wn * 32;
    int g = lane >> 2, q = lane & 3;
    size_t mbase = (size_t)blockIdx.x * 128;

    float* sa = (float*)(smem + DB_SA);
    float* sd = (float*)(smem + DB_SD);
    int* offH = (int*)(smem + DB_OFFH);
    uint32_t sb = smem_u32(smem);

    if (t < 128) {
        sa[t] = coef[t];
        sd[t] = coef[128 + t];
        if (fused) {
            int G = (int)mbase + t;
            int bn = G >> 4;
            int gi = idx[G];
            offH[t] = ((bn >> 10) * NN + gi) * CO;
        }
    }
    if (!fused) {
        #pragma unroll
        for (int kq = 0; kq < 4; kq++) {
            issue_raw(false, sb, X16, h16, nullptr, mbase, kq*32, kq, t);
            cp_commit();
        }
    }
    // load W into smem, rows stride 136 halves (68 u32)
    {
        const uint32_t* wh = reinterpret_cast<const uint32_t*>(Wh);
        uint32_t* bh = reinterpret_cast<uint32_t*>(smem + DB_BH);
        #pragma unroll
        for (int i = 0; i < 32; i++) {
            int e = t + 256*i;
            int c2 = e & 63, o = e >> 6;
            bh[o*68 + c2] = wh[e];
        }
    }
    if (fused) {
        __syncthreads();               // offH visible
        #pragma unroll
        for (int kq = 0; kq < 4; kq++) {
            issue_raw(true, sb, X16, h16, offH, mbase, kq*32, kq, t);
            cp_commit();
        }
        float* ctr = (float*)(smem + DB_CTR);
        int bn0 = blockIdx.x * 8;
        #pragma unroll
        for (int i = 0; i < 4; i++) {
            int e = t + 256*i;
            ctr[e] = center[bn0*CO + e];
        }
    }
    cp_wait<0>();
    __syncthreads();

    #pragma unroll
    for (int kq = 0; kq < 4; kq++)
        convert_raw(fused, smem, sa, sd, kq*32, kq, smem + DB_A + kq*10240, t);
    __syncthreads();

    uint32_t aOffLane = (uint32_t)((m0w + (lane & 15)) * 80 + ((lane >> 4) << 4));
    uint32_t bRow = (uint32_t)(n0w + (lane & 7) + ((lane >> 4) << 3));
    uint32_t bHiBase = sb + DB_BH + bRow * 272 + (((lane >> 3) & 1) << 4);

    float acc[4][4][4];
    #pragma unroll
    for (int a = 0; a < 4; a++)
        #pragma unroll
        for (int b = 0; b < 4; b++)
            #pragma unroll
            for (int r = 0; r < 4; r++) acc[a][b][r] = 0.f;

    // barrier-free mainloop: 8 k16 steps
    #pragma unroll
    for (int kq = 0; kq < 4; kq++) {
        uint32_t aHi = sb + DB_A + (uint32_t)(kq*10240) + aOffLane;
        #pragma unroll
        for (int ks = 0; ks < 2; ks++) {
            uint32_t koffA = (uint32_t)(ks * 32);
            uint32_t koffB = (uint32_t)(kq * 64 + ks * 32);
            uint32_t bh0[4], bh1[4];
            ldsm4(bh0, bHiBase + koffB);
            ldsm4(bh1, bHiBase + 16*272 + koffB);
            #pragma unroll
            for (int a = 0; a < 4; a++) {
                uint32_t ahi[4];
                ldsm4(ahi, aHi + (uint32_t)(a*16*80) + koffA);
                mma_f16(acc[a][0], ahi, bh0[0], bh0[1]);
                mma_f16(acc[a][1], ahi, bh0[2], bh0[3]);
                mma_f16(acc[a][2], ahi, bh1[0], bh1[1]);
                mma_f16(acc[a][3], ahi, bh1[2], bh1[3]);
            }
        }
    }

    // epilogue: store Y (fp16) + BN partials (fp32)
    float ls[4][2], lq[4][2];
    #pragma unroll
    for (int b = 0; b < 4; b++) { ls[b][0]=0.f; ls[b][1]=0.f; lq[b][0]=0.f; lq[b][1]=0.f; }
    #pragma unroll
    for (int a = 0; a < 4; a++) {
        #pragma unroll
        for (int hf = 0; hf < 2; hf++) {
            int row = m0w + 16*a + g + 8*hf;
            __half* yr = Y + (mbase + row)*CO + n0w + 2*q;
            #pragma unroll
            for (int b = 0; b < 4; b++) {
                float c0 = acc[a][b][2*hf], c1 = acc[a][b][2*hf + 1];
                *reinterpret_cast<uint32_t*>(yr + 8*b) =
                    packh2(__float2half_rn(c0), __float2half_rn(c1));
                ls[b][0] += c0; ls[b][1] += c1;
                lq[b][0] = fmaf(c0, c0, lq[b][0]);
                lq[b][1] = fmaf(c1, c1, lq[b][1]);
            }
        }
    }
    #pragma unroll
    for (int b = 0; b < 4; b++) {
        #pragma unroll
        for (int p2 = 0; p2 < 2; p2++) {
            #pragma unroll
            for (int off = 4; off < 32; off <<= 1) {
                ls[b][p2] += __shfl_xor_sync(0xffffffffu, ls[b][p2], off);
                lq[b][p2] += __shfl_xor_sync(0xffffffffu, lq[b][p2], off);
            }
        }
    }
    __syncthreads();   // all warps past mma before overlaying A
    float* redS = (float*)(smem + DB_A);
    float* redQ = (float*)(smem + DB_A + 4096);
    if (lane < 4) {
        #pragma unroll
        for (int b = 0; b < 4; b++) {
            #pragma unroll
            for (int p2 = 0; p2 < 2; p2++) {
                int cs = 8*b + 2*lane + p2;
                redS[wid*32 + cs] = ls[b][p2];
                redQ[wid*32 + cs] = lq[b][p2];
            }
        }
    }
    __syncthreads();
    if (t < 128) {
        int wnc = t >> 5, cw = t & 31;
        float Sv = redS[wnc*32 + cw] + redS[(wnc+4)*32 + cw];
        float Qv = redQ[wnc*32 + cw] + redQ[(wnc+4)*32 + cw];
        part[blockIdx.x*256 + t]       = Sv;
        part[blockIdx.x*256 + 128 + t] = Qv;
    }
}

__global__ __launch_bounds__(256, 2)
void gemm1_mma(const float* __restrict__ center, const __half* __restrict__ h16,
               const int* __restrict__ idx,
               const __half* __restrict__ Wh,
               const float* __restrict__ coef, __half* __restrict__ Y,
               float* __restrict__ part) {
    gemm_mma_core(true, nullptr, center, h16, idx, Wh, coef, Y, part);
}

__global__ __launch_bounds__(256, 2)
void gemm2_mma(const __half* __restrict__ X16,
               const __half* __restrict__ Wh,
               const float* __restrict__ coef, __half* __restrict__ Y,
               float* __restrict__ part) {
    gemm_mma_core(false, X16, nullptr, nullptr, nullptr, Wh, coef, Y, part);
}

// ------------------------- final: mean_k relu(bn2) + bn_sc + relu, transpose -
// grid 4096 = 32 b x 128 groups of 8 n-rows; x2 fp16 read as half2 (o-pairs).
__global__ void final_kernel(const __half* __restrict__ x2, const float* __restrict__ sc,
                             const float* __restrict__ coef2, const float* __restrict__ coefsc,
                             float* __restrict__ out) {
    __shared__ float tile[8*129];
    int t = threadIdx.x;
    int blk = blockIdx.x;
    int b = blk >> 7;
    int n0 = (blk & 127) << 3;
    #pragma unroll
    for (int i = 0; i < 2; i++) {
        int idx = t + 256*i;          // 512 o-pairs
        int op = idx & 63, nn = idx >> 6;
        int o = op << 1;
        int bn = b*NN + n0 + nn;
        float a20 = coef2[o],   d20 = coef2[128 + o];
        float a21 = coef2[o+1], d21 = coef2[128 + o + 1];
        const __half* xr = x2 + (size_t)bn * KNN * CO + o;
        float s0f = 0.f, s1f = 0.f;
        #pragma unroll
        for (int k = 0; k < KNN; k++) {
            __half2 hv = *reinterpret_cast<const __half2*>(xr + k*CO);
            float2 fv = __half22float2(hv);
            s0f += fmaxf(fmaf(a20, fv.x, d20), 0.f);
            s1f += fmaxf(fmaf(a21, fv.y, d21), 0.f);
        }
        float2 scv = *reinterpret_cast<const float2*>(sc + bn*CO + o);
        float as0 = coefsc[o],   ds0 = coefsc[128 + o];
        float as1 = coefsc[o+1], ds1 = coefsc[128 + o + 1];
        tile[nn*129 + o]     = fmaxf(fmaf(as0, scv.x, ds0) + s0f * (1.f/16.f), 0.f);
        tile[nn*129 + o + 1] = fmaxf(fmaf(as1, scv.y, ds1) + s1f * (1.f/16.f), 0.f);
    }
    __syncthreads();
    #pragma unroll
    for (int i = 0; i < 4; i++) {
        int idx = t + 256*i;
        int nn = idx & 7, o = idx >> 3;
        out[(size_t)b*CO*NN + o*NN + n0 + nn] = tile[nn*129 + o];
    }
}

// ------------------------- host launcher -------------------------------------
extern "C" void kernel_launch(void* const* d_in, const int* in_sizes, int n_in,
                              void* d_out, int out_size) {
    const float* points   = (const float*)d_in[0];
    const float* features = (const float*)d_in[1];
    const float* W0  = (const float*)d_in[2];
    const float* g0  = (const float*)d_in[3];
    const float* b0  = (const float*)d_in[4];
    const float* W1  = (const float*)d_in[5];
    const float* g1  = (const float*)d_in[6];
    const float* b1  = (const float*)d_in[7];
    const float* W2  = (const float*)d_in[8];
    const float* g2  = (const float*)d_in[9];
    const float* b2  = (const float*)d_in[10];
    const float* Wsc = (const float*)d_in[11];
    const float* gsc = (const float*)d_in[12];
    const float* bsc = (const float*)d_in[13];
    float* out = (float*)d_out;

    void *p_idx, *p_center, *p_h, *p_sc, *p_x1, *p_x2, *p_part, *p_partsc, *p_coef;
    void *p_w1h, *p_w2h;
    cudaGetSymbolAddress(&p_idx,    g_idx);
    cudaGetSymbolAddress(&p_center, g_center);
    cudaGetSymbolAddress(&p_h,      g_h);
    cudaGetSymbolAddress(&p_sc,     g_sc);
    cudaGetSymbolAddress(&p_x1,     g_x1);
    cudaGetSymbolAddress(&p_x2,     g_x2);
    cudaGetSymbolAddress(&p_part,   g_part);
    cudaGetSymbolAddress(&p_partsc, g_partsc);
    cudaGetSymbolAddress(&p_coef,   g_coef);
    cudaGetSymbolAddress(&p_w1h,    g_w1h);
    cudaGetSymbolAddress(&p_w2h,    g_w2h);

    int*    idx    = (int*)p_idx;
    float*  center = (float*)p_center;
    __half* h      = (__half*)p_h;
    float*  sc     = (float*)p_sc;
    __half* x1     = (__half*)p_x1;
    __half* x2     = (__half*)p_x2;
    float*  part   = (float*)p_part;
    float*  partsc = (float*)p_partsc;
    float*  coef0  = (float*)p_coef;
    float*  coef1  = coef0 + 256;
    float*  coef2  = coef0 + 512;
    float*  coef3  = coef0 + 768;
    __half* w1h = (__half*)p_w1h;
    __half* w2h = (__half*)p_w2h;

    const float invM  = 1.f / (float)ROWS;
    const float invMs = 1.f / (float)BNROWS;

    cudaFuncSetAttribute(gemm1_mma, cudaFuncAttributeMaxDynamicSharedMemorySize, DB_TOTAL);
    cudaFuncSetAttribute(gemm2_mma, cudaFuncAttributeMaxDynamicSharedMemorySize, DB_TOTAL);

    whalf_kernel<<<64, 256>>>(W1, W2, w1h, w2h);
    knn_kernel<<<GEMM_BLOCKS, 256>>>(points, idx);
    feat_kernel<<<BNROWS/16, 128>>>(features, W0, Wsc, center, h, sc);
    buildstats_kernel<<<GEMM_BLOCKS, 256>>>(center, h, idx, part);
    colpart_kernel<<<256, 256>>>(sc, partsc);
    stats_kernel<<<128, 256>>>(part, GEMM_BLOCKS, g0, b0, coef0, invM);
    stats_kernel<<<128, 256>>>(partsc, 256, gsc, bsc, coef3, invMs);
    gemm1_mma<<<GEMM_BLOCKS, 256, DB_TOTAL>>>(center, h, idx, w1h, coef0, x1, part);
    stats_kernel<<<128, 256>>>(part, GEMM_BLOCKS, g1, b1, coef1, invM);
    gemm2_mma<<<GEMM_BLOCKS, 256, DB_TOTAL>>>(x1, w2h, coef1, x2, part);
    stats_kernel<<<128, 256>>>(part, GEMM_BLOCKS, g2, b2, coef2, invM);
    final_kernel<<<4096, 256>>>(x2, sc, coef2, coef3, out);
}